// round 9
// baseline (speedup 1.0000x reference)
#include <cuda_runtime.h>
#include <cuda_bf16.h>
#include <math.h>

#define B_ 32
#define N_ 512
#define F_ 32
#define T_ 24
#define K_ 3
#define GC_ 64
#define TC_ 64

typedef unsigned long long ull;

// ---------------- scratch (device globals; no allocations allowed) ----------------
__device__ float g_rhs_tT[B_ * T_ * N_];
__device__ float g_tmp_part[B_ * 8 * 768];
__device__ float g_tmp_bt[B_ * T_ * F_];
__device__ float g_lhs_t[B_ * T_ * N_];
__device__ float g_temp_w[B_ * T_ * T_];
__device__ float g_xtemp[B_ * N_ * F_ * T_];
__device__ float g_lhs_s[B_ * N_ * T_];
__device__ float g_rhs_s[B_ * N_ * T_];
__device__ float g_S[B_ * N_ * N_];
__device__ float g_spat[B_ * N_ * N_];
__device__ float g_H[(size_t)B_ * K_ * N_ * F_ * T_];  // [(b*3+k), n, f*24+t]

// bf16 hi/lo operands, row-major [out-dim][m]
__device__ __nv_bfloat16 g_Ah16[(size_t)96 * 512 * 512];  // [(b*3+k)][n][m]
__device__ __nv_bfloat16 g_Al16[(size_t)96 * 512 * 512];
__device__ __nv_bfloat16 g_Xh16[(size_t)32 * 768 * 512];  // [b][j][m]
__device__ __nv_bfloat16 g_Xl16[(size_t)32 * 768 * 512];
// S-chain bf16 operands
__device__ __nv_bfloat16 g_projh[N_ * N_];                // [n][m]
__device__ __nv_bfloat16 g_projl[N_ * N_];
__device__ __nv_bfloat16 g_attnTh[(size_t)B_ * N_ * N_];  // [b][p][m] = attn[m][p]
__device__ __nv_bfloat16 g_attnTl[(size_t)B_ * N_ * N_];

// ---- bf16 mma helper ----
#define MMA16816(d, a, b)                                                            \
    asm volatile(                                                                    \
        "mma.sync.aligned.m16n8k16.row.col.f32.bf16.bf16.f32 "                       \
        "{%0,%1,%2,%3}, {%4,%5,%6,%7}, {%8,%9}, {%0,%1,%2,%3};"                      \
        : "+f"((d)[0]), "+f"((d)[1]), "+f"((d)[2]), "+f"((d)[3])                     \
        : "r"((a)[0]), "r"((a)[1]), "r"((a)[2]), "r"((a)[3]), "r"((b)[0]), "r"((b)[1]))

__device__ __forceinline__ unsigned bf16pair(float v0, float v1, float& r0, float& r1) {
    __nv_bfloat16 h0 = __float2bfloat16(v0), h1 = __float2bfloat16(v1);
    r0 = v0 - __bfloat162float(h0);
    r1 = v1 - __bfloat162float(h1);
    return (unsigned)__bfloat16_as_ushort(h0) | ((unsigned)__bfloat16_as_ushort(h1) << 16);
}

// ---------------- K1: rhs_tT ----------------
__global__ void rhs_t_kernel(const float* __restrict__ x, const float* __restrict__ w3) {
    int bn = blockIdx.x;
    int b = bn >> 9, n = bn & 511;
    __shared__ float row[768];
    const float* xr = x + (size_t)bn * 768;
    for (int i = threadIdx.x; i < 768; i += 128) row[i] = xr[i];
    __syncthreads();
    if (threadIdx.x < 24) {
        int t = threadIdx.x;
        float a = 0.f;
#pragma unroll
        for (int f = 0; f < 32; f++) a += w3[f] * row[f * 24 + t];
        g_rhs_tT[(b * 24 + t) * 512 + n] = a;
    }
}

// ---------------- K2a/b ----------------
__global__ void tmp_bt_part_kernel(const float* __restrict__ x, const float* __restrict__ w1) {
    int chunk = blockIdx.x;
    int b = blockIdx.y;
    int ft = threadIdx.x;
    const float* xb = x + (size_t)b * 512 * 768;
    int n0 = chunk * 64;
    float a = 0.f;
    for (int n = n0; n < n0 + 64; n++) a += w1[n] * xb[n * 768 + ft];
    g_tmp_part[(b * 8 + chunk) * 768 + ft] = a;
}
__global__ void tmp_bt_reduce_kernel() {
    int idx = blockIdx.x * blockDim.x + threadIdx.x;
    if (idx >= B_ * 768) return;
    int b = idx / 768, ft = idx % 768;
    float a = 0.f;
#pragma unroll
    for (int c = 0; c < 8; c++) a += g_tmp_part[(b * 8 + c) * 768 + ft];
    int f = ft / 24, t = ft - f * 24;
    g_tmp_bt[(b * 24 + t) * 32 + f] = a;
}

// ---------------- K3 ----------------
__global__ void lhs_t_kernel(const float* __restrict__ w2) {
    int idx = blockIdx.x * blockDim.x + threadIdx.x;
    if (idx >= B_ * T_ * N_) return;
    int n = idx & 511;
    int bt = idx >> 9;
    float a = 0.f;
#pragma unroll
    for (int f = 0; f < 32; f++) a += g_tmp_bt[bt * 32 + f] * w2[f * 512 + n];
    g_lhs_t[idx] = a;
}

// ---------------- K4 ----------------
__global__ void temporal_attn_kernel(const float* __restrict__ ta_bias,
                                     const float* __restrict__ ta_proj) {
    int b = blockIdx.x;
    int tid = threadIdx.x;
    int t = tid / 24, u = tid - (tid / 24) * 24;
    __shared__ float sL[24][129];
    __shared__ float sR[24][129];
    __shared__ float ssig[576];
    __shared__ float sE[576];

    float p = 0.f;
    for (int n0 = 0; n0 < 512; n0 += 128) {
        __syncthreads();
        for (int i = tid; i < 24 * 128; i += 576) {
            int tt = i >> 7, nn = i & 127;
            sL[tt][nn] = g_lhs_t[(b * 24 + tt) * 512 + n0 + nn];
            sR[tt][nn] = g_rhs_tT[(b * 24 + tt) * 512 + n0 + nn];
        }
        __syncthreads();
#pragma unroll 8
        for (int nn = 0; nn < 128; nn++) p += sL[t][nn] * sR[u][nn];
    }
    ssig[t * 24 + u] = 1.f / (1.f + expf(-(p + ta_bias[t * 24 + u])));
    __syncthreads();

    int s = t;
    float e = 0.f;
#pragma unroll
    for (int tt = 0; tt < 24; tt++) e += ta_proj[s * 24 + tt] * ssig[tt * 24 + u];
    sE[s * 24 + u] = e;
    __syncthreads();

    float mx = -1e30f;
#pragma unroll
    for (int ss = 0; ss < 24; ss++) mx = fmaxf(mx, sE[ss * 24 + u]);
    float sum = 0.f;
#pragma unroll
    for (int ss = 0; ss < 24; ss++) sum += expf(sE[ss * 24 + u] - mx);
    g_temp_w[b * 576 + s * 24 + u] = expf(e - mx) / sum;
}

// ---------------- K5 ----------------
__global__ void xtemp_kernel(const float* __restrict__ x) {
    int idx = blockIdx.x * blockDim.x + threadIdx.x;
    if (idx >= B_ * N_ * F_ * T_) return;
    int u = idx % 24;
    int row = idx / 24;
    int b = row / (512 * 32);
    const float* xr = x + (size_t)row * 24;
    const float* tw = g_temp_w + b * 576;
    float a = 0.f;
#pragma unroll
    for (int t = 0; t < 24; t++) a += xr[t] * tw[t * 24 + u];
    g_xtemp[idx] = a;
}

// ---------------- K6 ----------------
__global__ void spre_kernel(const float* __restrict__ wa, const float* __restrict__ wb,
                            const float* __restrict__ wc) {
    int bn = blockIdx.x;
    __shared__ float row[768];
    __shared__ float st2[32];
    const float* xr = g_xtemp + (size_t)bn * 768;
    for (int i = threadIdx.x; i < 768; i += 128) row[i] = xr[i];
    __syncthreads();
    if (threadIdx.x < 32) {
        int f = threadIdx.x;
        float a = 0.f;
#pragma unroll
        for (int t = 0; t < 24; t++) a += row[f * 24 + t] * wa[t];
        st2[f] = a;
    }
    __syncthreads();
    if (threadIdx.x < 24) {
        int t = threadIdx.x;
        float l = 0.f, r = 0.f;
#pragma unroll
        for (int f = 0; f < 32; f++) {
            l += st2[f] * wb[f * 24 + t];
            r += wc[f] * row[f * 24 + t];
        }
        g_lhs_s[bn * 24 + t] = l;
        g_rhs_s[bn * 24 + t] = r;
    }
}

// ---------------- conv_proj ----------------
__global__ void conv_proj_kernel(const float* __restrict__ proj) {
    int i = blockIdx.x * 256 + threadIdx.x;
    float v = proj[i];
    __nv_bfloat16 h = __float2bfloat16(v);
    g_projh[i] = h;
    g_projl[i] = __float2bfloat16(v - __bfloat162float(h));
}

// ---------------- K7: scores + sigmoid -> transposed bf16 hi/lo attnT[p][m] ----------------
__global__ void spatial_scores_kernel(const float* __restrict__ sa_bias) {
    int b = blockIdx.z;
    int n0 = blockIdx.y * 16, m0 = blockIdx.x * 16;
    __shared__ float sL[16 * 24], sR[16 * 24];
    __shared__ float tv[16][17];
    int tid = threadIdx.y * 16 + threadIdx.x;
    for (int i = tid; i < 384; i += 256) {
        sL[i] = g_lhs_s[(b * 512 + n0 + i / 24) * 24 + i % 24];
        sR[i] = g_rhs_s[(b * 512 + m0 + i / 24) * 24 + i % 24];
    }
    __syncthreads();
    int n = n0 + threadIdx.y, m = m0 + threadIdx.x;
    float s = 0.f;
#pragma unroll
    for (int t = 0; t < 24; t++) s += sL[threadIdx.y * 24 + t] * sR[threadIdx.x * 24 + t];
    float a = 1.f / (1.f + expf(-(s + sa_bias[n * 512 + m])));
    tv[threadIdx.x][threadIdx.y] = a;
    __syncthreads();
    float v = tv[threadIdx.y][threadIdx.x];
    __nv_bfloat16 h = __float2bfloat16(v);
    size_t o = ((size_t)b * 512 + m0 + threadIdx.y) * 512 + n0 + threadIdx.x;
    g_attnTh[o] = h;
    g_attnTl[o] = __float2bfloat16(v - __bfloat162float(h));
}

// ---------------- K8: S via bf16-split mma, 256 threads, tile 64n x 128p ----------------
// grid (pt 4, nt 8, b 32), 8 warps as 2n x 4p
__global__ void __launch_bounds__(256) S_mma_kernel() {
    __shared__ __align__(16) __nv_bfloat16 sP[2][64][40];
    __shared__ __align__(16) __nv_bfloat16 sB[2][128][40];
    int pt = blockIdx.x, nt = blockIdx.y, b = blockIdx.z;
    int n0 = nt * 64, p0 = pt * 128;
    int tid = threadIdx.x;
    int lane = tid & 31, wid = tid >> 5;
    int g = lane >> 2, tg = lane & 3;
    int wn = wid >> 2, wp = wid & 3;

    const __nv_bfloat16* srcP[2] = {g_projh + (size_t)n0 * 512, g_projl + (size_t)n0 * 512};
    const __nv_bfloat16* srcB[2] = {g_attnTh + ((size_t)b * 512 + p0) * 512,
                                    g_attnTl + ((size_t)b * 512 + p0) * 512};

    float d[2][4][4] = {};

    for (int m0 = 0; m0 < 512; m0 += 32) {
        for (int i = tid; i < 512; i += 256) {
            int rowid = i >> 2, quad = i & 3;
            int h = rowid >> 6, row = rowid & 63;
            *(uint4*)&sP[h][row][quad * 8] =
                *(const uint4*)(srcP[h] + (size_t)row * 512 + m0 + quad * 8);
        }
        for (int i = tid; i < 1024; i += 256) {
            int rowid = i >> 2, quad = i & 3;
            int h = rowid >> 7, row = rowid & 127;
            *(uint4*)&sB[h][row][quad * 8] =
                *(const uint4*)(srcB[h] + (size_t)row * 512 + m0 + quad * 8);
        }
        __syncthreads();

#pragma unroll
        for (int kk = 0; kk < 32; kk += 16) {
            unsigned bh[4][2], bl[4][2];
#pragma unroll
            for (int p4 = 0; p4 < 4; p4++) {
                int pr = wp * 32 + p4 * 8 + g;
                bh[p4][0] = *(const unsigned*)&sB[0][pr][kk + tg * 2];
                bh[p4][1] = *(const unsigned*)&sB[0][pr][kk + tg * 2 + 8];
                bl[p4][0] = *(const unsigned*)&sB[1][pr][kk + tg * 2];
                bl[p4][1] = *(const unsigned*)&sB[1][pr][kk + tg * 2 + 8];
            }
#pragma unroll
            for (int mt = 0; mt < 2; mt++) {
                int r0 = wn * 32 + mt * 16 + g;
                unsigned ah[4], al[4];
                ah[0] = *(const unsigned*)&sP[0][r0][kk + tg * 2];
                ah[1] = *(const unsigned*)&sP[0][r0 + 8][kk + tg * 2];
                ah[2] = *(const unsigned*)&sP[0][r0][kk + tg * 2 + 8];
                ah[3] = *(const unsigned*)&sP[0][r0 + 8][kk + tg * 2 + 8];
                al[0] = *(const unsigned*)&sP[1][r0][kk + tg * 2];
                al[1] = *(const unsigned*)&sP[1][r0 + 8][kk + tg * 2];
                al[2] = *(const unsigned*)&sP[1][r0][kk + tg * 2 + 8];
                al[3] = *(const unsigned*)&sP[1][r0 + 8][kk + tg * 2 + 8];
#pragma unroll
                for (int p4 = 0; p4 < 4; p4++) {
                    MMA16816(d[mt][p4], ah, bh[p4]);
                    MMA16816(d[mt][p4], ah, bl[p4]);
                    MMA16816(d[mt][p4], al, bh[p4]);
                }
            }
        }
        __syncthreads();
    }

    float* Sb = g_S + (size_t)b * 262144;
#pragma unroll
    for (int mt = 0; mt < 2; mt++) {
        int nrow = n0 + wn * 32 + mt * 16 + g;
#pragma unroll
        for (int p4 = 0; p4 < 4; p4++) {
            int pcol = p0 + wp * 32 + p4 * 8 + tg * 2;
            *(float2*)&Sb[(size_t)nrow * 512 + pcol] = make_float2(d[mt][p4][0], d[mt][p4][1]);
            *(float2*)&Sb[(size_t)(nrow + 8) * 512 + pcol] = make_float2(d[mt][p4][2], d[mt][p4][3]);
        }
    }
}

// ---------------- K9: column softmax ----------------
__global__ void spat_softmax_kernel() {
    int idx = blockIdx.x * blockDim.x + threadIdx.x;
    if (idx >= B_ * N_) return;
    int b = idx >> 9, p = idx & 511;
    const float* base = g_S + (size_t)b * 262144 + p;
    float* ob = g_spat + (size_t)b * 262144 + p;
    float mx = -1e30f;
    for (int n = 0; n < 512; n++) mx = fmaxf(mx, base[n * 512]);
    float sum = 0.f;
    for (int n = 0; n < 512; n++) {
        float e = expf(base[n * 512] - mx);
        sum += e;
        ob[n * 512] = e;
    }
    float inv = 1.f / sum;
    for (int n = 0; n < 512; n++) ob[n * 512] *= inv;
}

// ---------------- convA ----------------
__global__ void convA_kernel(const float* __restrict__ cheb) {
    int bk = blockIdx.z;
    int b = bk / 3, k = bk - b * 3;
    int m0 = blockIdx.x * 32, n0 = blockIdx.y * 32;
    __shared__ float tile[32][33];
    const float* ck = cheb + (size_t)k * 262144;
    const float* sp = g_spat + (size_t)b * 262144;
#pragma unroll
    for (int r = 0; r < 4; r++) {
        int m = m0 + threadIdx.y + r * 8;
        int gi = m * 512 + n0 + threadIdx.x;
        tile[threadIdx.y + r * 8][threadIdx.x] = ck[gi] * sp[gi];
    }
    __syncthreads();
    int tid = threadIdx.y * 32 + threadIdx.x;
    unsigned* oh = (unsigned*)g_Ah16;
    unsigned* ol = (unsigned*)g_Al16;
#pragma unroll
    for (int p = 0; p < 2; p++) {
        int pi = tid + p * 256;
        int row = pi >> 4;
        int cp = pi & 15;
        float r0, r1;
        unsigned uh = bf16pair(tile[2 * cp][row], tile[2 * cp + 1][row], r0, r1);
        __nv_bfloat16 l0 = __float2bfloat16(r0), l1 = __float2bfloat16(r1);
        unsigned ulv = (unsigned)__bfloat16_as_ushort(l0) |
                       ((unsigned)__bfloat16_as_ushort(l1) << 16);
        size_t base = ((size_t)bk * 512 + n0 + row) * 256 + (m0 >> 1) + cp;
        oh[base] = uh;
        ol[base] = ulv;
    }
}

// ---------------- convX ----------------
__global__ void convX_kernel(const float* __restrict__ x) {
    int b = blockIdx.z;
    int m0 = blockIdx.x * 32, j0 = blockIdx.y * 32;
    __shared__ float tile[32][33];
    const float* xb = x + (size_t)b * 393216;
#pragma unroll
    for (int r = 0; r < 4; r++) {
        int m = m0 + threadIdx.y + r * 8;
        tile[threadIdx.y + r * 8][threadIdx.x] = xb[m * 768 + j0 + threadIdx.x];
    }
    __syncthreads();
    int tid = threadIdx.y * 32 + threadIdx.x;
    unsigned* oh = (unsigned*)g_Xh16;
    unsigned* ol = (unsigned*)g_Xl16;
#pragma unroll
    for (int p = 0; p < 2; p++) {
        int pi = tid + p * 256;
        int row = pi >> 4;
        int cp = pi & 15;
        float r0, r1;
        unsigned uh = bf16pair(tile[2 * cp][row], tile[2 * cp + 1][row], r0, r1);
        __nv_bfloat16 l0 = __float2bfloat16(r0), l1 = __float2bfloat16(r1);
        unsigned ulv = (unsigned)__bfloat16_as_ushort(l0) |
                       ((unsigned)__bfloat16_as_ushort(l1) << 16);
        size_t base = ((size_t)b * 768 + j0 + row) * 256 + (m0 >> 1) + cp;
        oh[base] = uh;
        ol[base] = ulv;
    }
}

// ---------------- cheb MMA: 256 threads, tile 64n x 128j ----------------
// grid (jt 6, nt 8, b 32), 8 warps as 2n x 4j
__global__ void __launch_bounds__(256) cheb_mma_kernel() {
    __shared__ __align__(16) __nv_bfloat16 sA[3][2][64][40];
    __shared__ __align__(16) __nv_bfloat16 sX[2][128][40];
    int jt = blockIdx.x, nt = blockIdx.y, b = blockIdx.z;
    int n0 = nt * 64, j0 = jt * 128;
    int tid = threadIdx.x;
    int lane = tid & 31, wid = tid >> 5;
    int g = lane >> 2, tg = lane & 3;
    int wn = wid >> 2, wj = wid & 3;

    const __nv_bfloat16* srcA[6];
#pragma unroll
    for (int c = 0; c < 3; c++) {
        size_t base = ((size_t)(b * 3 + c) * 512 + n0) * 512;
        srcA[c * 2] = g_Ah16 + base;
        srcA[c * 2 + 1] = g_Al16 + base;
    }
    const __nv_bfloat16* srcXh = g_Xh16 + ((size_t)b * 768 + j0) * 512;
    const __nv_bfloat16* srcXl = g_Xl16 + ((size_t)b * 768 + j0) * 512;

    float d[3][2][4][4] = {};

    for (int m0 = 0; m0 < 512; m0 += 32) {
        for (int i = tid; i < 1536; i += 256) {
            int rowid = i >> 2, quad = i & 3;
            int ch = rowid >> 6;
            int row = rowid & 63;
            uint4 v = *(const uint4*)(srcA[ch] + (size_t)row * 512 + m0 + quad * 8);
            *(uint4*)&sA[ch >> 1][ch & 1][row][quad * 8] = v;
        }
        for (int i = tid; i < 1024; i += 256) {
            int rowid = i >> 2, quad = i & 3;
            int h = rowid >> 7, row = rowid & 127;
            const __nv_bfloat16* sp = (h ? srcXl : srcXh) + (size_t)row * 512 + m0 + quad * 8;
            *(uint4*)&sX[h][row][quad * 8] = *(const uint4*)sp;
        }
        __syncthreads();

#pragma unroll
        for (int kk = 0; kk < 32; kk += 16) {
            unsigned xh[4][2], xl[4][2];
#pragma unroll
            for (int ntile = 0; ntile < 4; ntile++) {
                int jr = wj * 32 + ntile * 8 + g;
                xh[ntile][0] = *(const unsigned*)&sX[0][jr][kk + tg * 2];
                xh[ntile][1] = *(const unsigned*)&sX[0][jr][kk + tg * 2 + 8];
                xl[ntile][0] = *(const unsigned*)&sX[1][jr][kk + tg * 2];
                xl[ntile][1] = *(const unsigned*)&sX[1][jr][kk + tg * 2 + 8];
            }
#pragma unroll
            for (int c = 0; c < 3; c++) {
#pragma unroll
                for (int mt = 0; mt < 2; mt++) {
                    int r0 = wn * 32 + mt * 16 + g;
                    unsigned ah[4], al[4];
                    ah[0] = *(const unsigned*)&sA[c][0][r0][kk + tg * 2];
                    ah[1] = *(const unsigned*)&sA[c][0][r0 + 8][kk + tg * 2];
                    ah[2] = *(const unsigned*)&sA[c][0][r0][kk + tg * 2 + 8];
                    ah[3] = *(const unsigned*)&sA[c][0][r0 + 8][kk + tg * 2 + 8];
                    al[0] = *(const unsigned*)&sA[c][1][r0][kk + tg * 2];
                    al[1] = *(const unsigned*)&sA[c][1][r0 + 8][kk + tg * 2];
                    al[2] = *(const unsigned*)&sA[c][1][r0][kk + tg * 2 + 8];
                    al[3] = *(const unsigned*)&sA[c][1][r0 + 8][kk + tg * 2 + 8];
#pragma unroll
                    for (int ntile = 0; ntile < 4; ntile++) {
                        MMA16816(d[c][mt][ntile], ah, xh[ntile]);
                        MMA16816(d[c][mt][ntile], ah, xl[ntile]);
                        MMA16816(d[c][mt][ntile], al, xh[ntile]);
                    }
                }
            }
        }
        __syncthreads();
    }

#pragma unroll
    for (int c = 0; c < 3; c++) {
        float* Hb = g_H + (size_t)(b * 3 + c) * 512 * 768;
#pragma unroll
        for (int mt = 0; mt < 2; mt++) {
            int nrow = n0 + wn * 32 + mt * 16 + g;
#pragma unroll
            for (int ntile = 0; ntile < 4; ntile++) {
                int jcol = j0 + wj * 32 + ntile * 8 + tg * 2;
                float2 v0 = make_float2(d[c][mt][ntile][0], d[c][mt][ntile][1]);
                float2 v1 = make_float2(d[c][mt][ntile][2], d[c][mt][ntile][3]);
                *(float2*)&Hb[(size_t)nrow * 768 + jcol] = v0;
                *(float2*)&Hb[(size_t)(nrow + 8) * 768 + jcol] = v1;
            }
        }
    }
}

// ---------------- K11: fused epilogue, 192 threads (64ch x 3 t-thirds) ----------------
__global__ void __launch_bounds__(192) final_kernel(
    const float* __restrict__ x, const float* __restrict__ w_cheb,
    const float* __restrict__ time_w, const float* __restrict__ time_b,
    const float* __restrict__ skip_w, const float* __restrict__ skip_b,
    const float* __restrict__ ln_g, const float* __restrict__ ln_b,
    float* __restrict__ out) {
    int bn = blockIdx.x;
    int b = bn >> 9, n = bn & 511;
    int tid = threadIdx.x;  // 192
    int third = tid / 64, ch = tid & 63;
    int tbase = third * 8;
    __shared__ float sH[3 * 32 * 24];
    __shared__ float sx[768];
    __shared__ float sg[64][26];
    __shared__ float sv[64 * 24];
    __shared__ float smu[24], srs[24];

    for (int k = 0; k < 3; k++) {
        const float* src = g_H + ((size_t)(b * 3 + k) * 512 + n) * 768;
        for (int i = tid; i < 768; i += 192) sH[k * 768 + i] = src[i];
    }
    const float* xrow = x + (size_t)bn * 768;
    for (int i = tid; i < 768; i += 192) sx[i] = xrow[i];
    __syncthreads();

    {
        float acc[8];
#pragma unroll
        for (int t = 0; t < 8; t++) acc[t] = 0.f;
        for (int kf = 0; kf < 96; kf++) {
            float w = w_cheb[kf * 64 + ch];
            const float* hr = &sH[kf * 24 + tbase];
#pragma unroll
            for (int t = 0; t < 8; t++) acc[t] += hr[t] * w;
        }
        if (third == 0) sg[ch][0] = 0.f;
        if (third == 2) sg[ch][25] = 0.f;
#pragma unroll
        for (int t = 0; t < 8; t++) sg[ch][tbase + t + 1] = fmaxf(acc[t], 0.f);
    }
    __syncthreads();

    {
        float acc[8];
#pragma unroll
        for (int t = 0; t < 8; t++) acc[t] = 0.f;
        for (int g = 0; g < 64; g++) {
            float w0 = time_w[(ch * 64 + g) * 3 + 0];
            float w1 = time_w[(ch * 64 + g) * 3 + 1];
            float w2 = time_w[(ch * 64 + g) * 3 + 2];
            const float* gr = &sg[g][tbase];
#pragma unroll
            for (int t = 0; t < 8; t++) acc[t] += gr[t] * w0 + gr[t + 1] * w1 + gr[t + 2] * w2;
        }
        for (int f = 0; f < 32; f++) {
            float w = skip_w[ch * 32 + f];
            const float* xr = &sx[f * 24 + tbase];
#pragma unroll
            for (int t = 0; t < 8; t++) acc[t] += xr[t] * w;
        }
        float bias = time_b[ch] + skip_b[ch];
#pragma unroll
        for (int t = 0; t < 8; t++) sv[ch * 24 + tbase + t] = fmaxf(acc[t] + bias, 0.f);
    }
    __syncthreads();

    if (tid < 24) {
        int t = tid;
        float s = 0.f, s2 = 0.f;
        for (int c = 0; c < 64; c++) {
            float v = sv[c * 24 + t];
            s += v;
            s2 += v * v;
        }
        float mu = s * (1.f / 64.f);
        float var = s2 * (1.f / 64.f) - mu * mu;
        smu[t] = mu;
        srs[t] = rsqrtf(var + 1e-5f);
    }
    __syncthreads();

    float* orow = out + (size_t)bn * 1536;
    for (int i = tid; i < 1536; i += 192) {
        int c = i / 24, t = i - c * 24;
        orow[i] = (sv[i] - smu[t]) * srs[t] * ln_g[c] + ln_b[c];
    }
}

// ---------------- launch ----------------
extern "C" void kernel_launch(void* const* d_in, const int* in_sizes, int n_in,
                              void* d_out, int out_size) {
    const float* x       = (const float*)d_in[0];
    const float* cheb    = (const float*)d_in[1];
    const float* w_cheb  = (const float*)d_in[2];
    const float* sa_wa   = (const float*)d_in[3];
    const float* sa_wb   = (const float*)d_in[4];
    const float* sa_wc   = (const float*)d_in[5];
    const float* sa_bias = (const float*)d_in[6];
    const float* sa_proj = (const float*)d_in[7];
    const float* ta_w1   = (const float*)d_in[8];
    const float* ta_w2   = (const float*)d_in[9];
    const float* ta_w3   = (const float*)d_in[10];
    const float* ta_bias = (const float*)d_in[11];
    const float* ta_proj = (const float*)d_in[12];
    const float* time_w  = (const float*)d_in[13];
    const float* time_b  = (const float*)d_in[14];
    const float* skip_w  = (const float*)d_in[15];
    const float* skip_b  = (const float*)d_in[16];
    const float* ln_g    = (const float*)d_in[17];
    const float* ln_b    = (const float*)d_in[18];
    float* out = (float*)d_out;

    // temporal attention
    rhs_t_kernel<<<B_ * N_, 128>>>(x, ta_w3);
    tmp_bt_part_kernel<<<dim3(8, B_), 768>>>(x, ta_w1);
    tmp_bt_reduce_kernel<<<(B_ * 768 + 255) / 256, 256>>>();
    lhs_t_kernel<<<(B_ * T_ * N_ + 255) / 256, 256>>>(ta_w2);
    temporal_attn_kernel<<<B_, 576>>>(ta_bias, ta_proj);
    xtemp_kernel<<<(B_ * N_ * F_ * T_ + 255) / 256, 256>>>(x);

    // operand conversions independent of the attention chain
    convX_kernel<<<dim3(16, 24, B_), dim3(32, 8)>>>(x);
    conv_proj_kernel<<<1024, 256>>>(sa_proj);

    // spatial attention (bf16-split mma S chain)
    spre_kernel<<<B_ * N_, 128>>>(sa_wa, sa_wb, sa_wc);
    spatial_scores_kernel<<<dim3(32, 32, B_), dim3(16, 16)>>>(sa_bias);
    S_mma_kernel<<<dim3(4, 8, B_), 256>>>();
    spat_softmax_kernel<<<(B_ * N_ + 255) / 256, 256>>>();

    // chebyshev graph conv via bf16-split mma.sync
    convA_kernel<<<dim3(16, 16, 96), dim3(32, 8)>>>(cheb);
    cheb_mma_kernel<<<dim3(6, 8, B_), 256>>>();

    // fused epilogue
    final_kernel<<<B_ * N_, 192>>>(x, w_cheb, time_w, time_b, skip_w, skip_b, ln_g, ln_b, out);
}

// round 10
// speedup vs baseline: 1.0250x; 1.0250x over previous
#include <cuda_runtime.h>
#include <cuda_bf16.h>
#include <math.h>

#define B_ 32
#define N_ 512
#define F_ 32
#define T_ 24
#define K_ 3
#define GC_ 64
#define TC_ 64

typedef unsigned long long ull;

// ---------------- scratch (device globals; no allocations allowed) ----------------
__device__ float g_rhs_tT[B_ * T_ * N_];
__device__ float g_tmp_part[B_ * 8 * 768];
__device__ float g_tmp_bt[B_ * T_ * F_];
__device__ float g_lhs_t[B_ * T_ * N_];
__device__ float g_temp_w[B_ * T_ * T_];
__device__ float g_xtemp[B_ * N_ * F_ * T_];
__device__ float g_lhs_s[B_ * N_ * T_];
__device__ float g_rhs_s[B_ * N_ * T_];
__device__ float g_S[B_ * N_ * N_];
__device__ float g_spat[B_ * N_ * N_];
__device__ float g_H[(size_t)B_ * K_ * N_ * F_ * T_];  // [(b*3+k), n, f*24+t]

// bf16 hi/lo operands, row-major [out-dim][m]
__device__ __nv_bfloat16 g_Ah16[(size_t)96 * 512 * 512];  // [(b*3+k)][n][m]
__device__ __nv_bfloat16 g_Al16[(size_t)96 * 512 * 512];
__device__ __nv_bfloat16 g_Xh16[(size_t)32 * 768 * 512];  // [b][j][m]
__device__ __nv_bfloat16 g_Xl16[(size_t)32 * 768 * 512];
// S-chain bf16 operands
__device__ __nv_bfloat16 g_projh[N_ * N_];                // [n][m]
__device__ __nv_bfloat16 g_projl[N_ * N_];
__device__ __nv_bfloat16 g_attnTh[(size_t)B_ * N_ * N_];  // [b][p][m] = attn[m][p]
__device__ __nv_bfloat16 g_attnTl[(size_t)B_ * N_ * N_];

// ---- bf16 mma helper ----
#define MMA16816(d, a, b)                                                            \
    asm volatile(                                                                    \
        "mma.sync.aligned.m16n8k16.row.col.f32.bf16.bf16.f32 "                       \
        "{%0,%1,%2,%3}, {%4,%5,%6,%7}, {%8,%9}, {%0,%1,%2,%3};"                      \
        : "+f"((d)[0]), "+f"((d)[1]), "+f"((d)[2]), "+f"((d)[3])                     \
        : "r"((a)[0]), "r"((a)[1]), "r"((a)[2]), "r"((a)[3]), "r"((b)[0]), "r"((b)[1]))

__device__ __forceinline__ unsigned bf16pair(float v0, float v1, float& r0, float& r1) {
    __nv_bfloat16 h0 = __float2bfloat16(v0), h1 = __float2bfloat16(v1);
    r0 = v0 - __bfloat162float(h0);
    r1 = v1 - __bfloat162float(h1);
    return (unsigned)__bfloat16_as_ushort(h0) | ((unsigned)__bfloat16_as_ushort(h1) << 16);
}

// ---------------- K1: rhs_tT ----------------
__global__ void rhs_t_kernel(const float* __restrict__ x, const float* __restrict__ w3) {
    int bn = blockIdx.x;
    int b = bn >> 9, n = bn & 511;
    __shared__ float row[768];
    const float* xr = x + (size_t)bn * 768;
    for (int i = threadIdx.x; i < 768; i += 128) row[i] = xr[i];
    __syncthreads();
    if (threadIdx.x < 24) {
        int t = threadIdx.x;
        float a = 0.f;
#pragma unroll
        for (int f = 0; f < 32; f++) a += w3[f] * row[f * 24 + t];
        g_rhs_tT[(b * 24 + t) * 512 + n] = a;
    }
}

// ---------------- K2a/b ----------------
__global__ void tmp_bt_part_kernel(const float* __restrict__ x, const float* __restrict__ w1) {
    int chunk = blockIdx.x;
    int b = blockIdx.y;
    int ft = threadIdx.x;
    const float* xb = x + (size_t)b * 512 * 768;
    int n0 = chunk * 64;
    float a = 0.f;
    for (int n = n0; n < n0 + 64; n++) a += w1[n] * xb[n * 768 + ft];
    g_tmp_part[(b * 8 + chunk) * 768 + ft] = a;
}
__global__ void tmp_bt_reduce_kernel() {
    int idx = blockIdx.x * blockDim.x + threadIdx.x;
    if (idx >= B_ * 768) return;
    int b = idx / 768, ft = idx % 768;
    float a = 0.f;
#pragma unroll
    for (int c = 0; c < 8; c++) a += g_tmp_part[(b * 8 + c) * 768 + ft];
    int f = ft / 24, t = ft - f * 24;
    g_tmp_bt[(b * 24 + t) * 32 + f] = a;
}

// ---------------- K3 ----------------
__global__ void lhs_t_kernel(const float* __restrict__ w2) {
    int idx = blockIdx.x * blockDim.x + threadIdx.x;
    if (idx >= B_ * T_ * N_) return;
    int n = idx & 511;
    int bt = idx >> 9;
    float a = 0.f;
#pragma unroll
    for (int f = 0; f < 32; f++) a += g_tmp_bt[bt * 32 + f] * w2[f * 512 + n];
    g_lhs_t[idx] = a;
}

// ---------------- K4 ----------------
__global__ void temporal_attn_kernel(const float* __restrict__ ta_bias,
                                     const float* __restrict__ ta_proj) {
    int b = blockIdx.x;
    int tid = threadIdx.x;
    int t = tid / 24, u = tid - (tid / 24) * 24;
    __shared__ float sL[24][129];
    __shared__ float sR[24][129];
    __shared__ float ssig[576];
    __shared__ float sE[576];

    float p = 0.f;
    for (int n0 = 0; n0 < 512; n0 += 128) {
        __syncthreads();
        for (int i = tid; i < 24 * 128; i += 576) {
            int tt = i >> 7, nn = i & 127;
            sL[tt][nn] = g_lhs_t[(b * 24 + tt) * 512 + n0 + nn];
            sR[tt][nn] = g_rhs_tT[(b * 24 + tt) * 512 + n0 + nn];
        }
        __syncthreads();
#pragma unroll 8
        for (int nn = 0; nn < 128; nn++) p += sL[t][nn] * sR[u][nn];
    }
    ssig[t * 24 + u] = 1.f / (1.f + expf(-(p + ta_bias[t * 24 + u])));
    __syncthreads();

    int s = t;
    float e = 0.f;
#pragma unroll
    for (int tt = 0; tt < 24; tt++) e += ta_proj[s * 24 + tt] * ssig[tt * 24 + u];
    sE[s * 24 + u] = e;
    __syncthreads();

    float mx = -1e30f;
#pragma unroll
    for (int ss = 0; ss < 24; ss++) mx = fmaxf(mx, sE[ss * 24 + u]);
    float sum = 0.f;
#pragma unroll
    for (int ss = 0; ss < 24; ss++) sum += expf(sE[ss * 24 + u] - mx);
    g_temp_w[b * 576 + s * 24 + u] = expf(e - mx) / sum;
}

// ---------------- K5 ----------------
__global__ void xtemp_kernel(const float* __restrict__ x) {
    int idx = blockIdx.x * blockDim.x + threadIdx.x;
    if (idx >= B_ * N_ * F_ * T_) return;
    int u = idx % 24;
    int row = idx / 24;
    int b = row / (512 * 32);
    const float* xr = x + (size_t)row * 24;
    const float* tw = g_temp_w + b * 576;
    float a = 0.f;
#pragma unroll
    for (int t = 0; t < 24; t++) a += xr[t] * tw[t * 24 + u];
    g_xtemp[idx] = a;
}

// ---------------- K6 ----------------
__global__ void spre_kernel(const float* __restrict__ wa, const float* __restrict__ wb,
                            const float* __restrict__ wc) {
    int bn = blockIdx.x;
    __shared__ float row[768];
    __shared__ float st2[32];
    const float* xr = g_xtemp + (size_t)bn * 768;
    for (int i = threadIdx.x; i < 768; i += 128) row[i] = xr[i];
    __syncthreads();
    if (threadIdx.x < 32) {
        int f = threadIdx.x;
        float a = 0.f;
#pragma unroll
        for (int t = 0; t < 24; t++) a += row[f * 24 + t] * wa[t];
        st2[f] = a;
    }
    __syncthreads();
    if (threadIdx.x < 24) {
        int t = threadIdx.x;
        float l = 0.f, r = 0.f;
#pragma unroll
        for (int f = 0; f < 32; f++) {
            l += st2[f] * wb[f * 24 + t];
            r += wc[f] * row[f * 24 + t];
        }
        g_lhs_s[bn * 24 + t] = l;
        g_rhs_s[bn * 24 + t] = r;
    }
}

// ---------------- conv_proj ----------------
__global__ void conv_proj_kernel(const float* __restrict__ proj) {
    int i = blockIdx.x * 256 + threadIdx.x;
    float v = proj[i];
    __nv_bfloat16 h = __float2bfloat16(v);
    g_projh[i] = h;
    g_projl[i] = __float2bfloat16(v - __bfloat162float(h));
}

// ---------------- K7: scores + sigmoid -> transposed bf16 hi/lo attnT[p][m] ----------------
__global__ void spatial_scores_kernel(const float* __restrict__ sa_bias) {
    int b = blockIdx.z;
    int n0 = blockIdx.y * 16, m0 = blockIdx.x * 16;
    __shared__ float sL[16 * 24], sR[16 * 24];
    __shared__ float tv[16][17];
    int tid = threadIdx.y * 16 + threadIdx.x;
    for (int i = tid; i < 384; i += 256) {
        sL[i] = g_lhs_s[(b * 512 + n0 + i / 24) * 24 + i % 24];
        sR[i] = g_rhs_s[(b * 512 + m0 + i / 24) * 24 + i % 24];
    }
    __syncthreads();
    int n = n0 + threadIdx.y, m = m0 + threadIdx.x;
    float s = 0.f;
#pragma unroll
    for (int t = 0; t < 24; t++) s += sL[threadIdx.y * 24 + t] * sR[threadIdx.x * 24 + t];
    float a = 1.f / (1.f + expf(-(s + sa_bias[n * 512 + m])));
    tv[threadIdx.x][threadIdx.y] = a;
    __syncthreads();
    float v = tv[threadIdx.y][threadIdx.x];
    __nv_bfloat16 h = __float2bfloat16(v);
    size_t o = ((size_t)b * 512 + m0 + threadIdx.y) * 512 + n0 + threadIdx.x;
    g_attnTh[o] = h;
    g_attnTl[o] = __float2bfloat16(v - __bfloat162float(h));
}

// ---------------- K8: S via bf16-split mma (R8 128-thread version) ----------------
// grid (pt 8, nt 8, b 32), 128 threads (4 warps 2n x 2p), tile 64n x 64p
__global__ void __launch_bounds__(128) S_mma_kernel() {
    __shared__ __align__(16) __nv_bfloat16 sP[2][64][40];
    __shared__ __align__(16) __nv_bfloat16 sB[2][64][40];
    int pt = blockIdx.x, nt = blockIdx.y, b = blockIdx.z;
    int n0 = nt * 64, p0 = pt * 64;
    int tid = threadIdx.x;
    int lane = tid & 31, wid = tid >> 5;
    int g = lane >> 2, tg = lane & 3;
    int wn = wid >> 1, wp = wid & 1;

    const __nv_bfloat16* srcP[2] = {g_projh + (size_t)n0 * 512, g_projl + (size_t)n0 * 512};
    const __nv_bfloat16* srcB[2] = {g_attnTh + ((size_t)b * 512 + p0) * 512,
                                    g_attnTl + ((size_t)b * 512 + p0) * 512};

    float d[2][4][4] = {};

    for (int m0 = 0; m0 < 512; m0 += 32) {
        for (int i = tid; i < 512; i += 128) {
            int rowid = i >> 2, quad = i & 3;
            int h = rowid >> 6, row = rowid & 63;
            *(uint4*)&sP[h][row][quad * 8] =
                *(const uint4*)(srcP[h] + (size_t)row * 512 + m0 + quad * 8);
        }
        for (int i = tid; i < 512; i += 128) {
            int rowid = i >> 2, quad = i & 3;
            int h = rowid >> 6, row = rowid & 63;
            *(uint4*)&sB[h][row][quad * 8] =
                *(const uint4*)(srcB[h] + (size_t)row * 512 + m0 + quad * 8);
        }
        __syncthreads();

#pragma unroll
        for (int kk = 0; kk < 32; kk += 16) {
            unsigned bh[4][2], bl[4][2];
#pragma unroll
            for (int p4 = 0; p4 < 4; p4++) {
                int pr = wp * 32 + p4 * 8 + g;
                bh[p4][0] = *(const unsigned*)&sB[0][pr][kk + tg * 2];
                bh[p4][1] = *(const unsigned*)&sB[0][pr][kk + tg * 2 + 8];
                bl[p4][0] = *(const unsigned*)&sB[1][pr][kk + tg * 2];
                bl[p4][1] = *(const unsigned*)&sB[1][pr][kk + tg * 2 + 8];
            }
#pragma unroll
            for (int mt = 0; mt < 2; mt++) {
                int r0 = wn * 32 + mt * 16 + g;
                unsigned ah[4], al[4];
                ah[0] = *(const unsigned*)&sP[0][r0][kk + tg * 2];
                ah[1] = *(const unsigned*)&sP[0][r0 + 8][kk + tg * 2];
                ah[2] = *(const unsigned*)&sP[0][r0][kk + tg * 2 + 8];
                ah[3] = *(const unsigned*)&sP[0][r0 + 8][kk + tg * 2 + 8];
                al[0] = *(const unsigned*)&sP[1][r0][kk + tg * 2];
                al[1] = *(const unsigned*)&sP[1][r0 + 8][kk + tg * 2];
                al[2] = *(const unsigned*)&sP[1][r0][kk + tg * 2 + 8];
                al[3] = *(const unsigned*)&sP[1][r0 + 8][kk + tg * 2 + 8];
#pragma unroll
                for (int p4 = 0; p4 < 4; p4++) {
                    MMA16816(d[mt][p4], ah, bh[p4]);
                    MMA16816(d[mt][p4], ah, bl[p4]);
                    MMA16816(d[mt][p4], al, bh[p4]);
                }
            }
        }
        __syncthreads();
    }

    float* Sb = g_S + (size_t)b * 262144;
#pragma unroll
    for (int mt = 0; mt < 2; mt++) {
        int nrow = n0 + wn * 32 + mt * 16 + g;
#pragma unroll
        for (int p4 = 0; p4 < 4; p4++) {
            int pcol = p0 + wp * 32 + p4 * 8 + tg * 2;
            *(float2*)&Sb[(size_t)nrow * 512 + pcol] = make_float2(d[mt][p4][0], d[mt][p4][1]);
            *(float2*)&Sb[(size_t)(nrow + 8) * 512 + pcol] = make_float2(d[mt][p4][2], d[mt][p4][3]);
        }
    }
}

// ---------------- K9: column softmax ----------------
__global__ void spat_softmax_kernel() {
    int idx = blockIdx.x * blockDim.x + threadIdx.x;
    if (idx >= B_ * N_) return;
    int b = idx >> 9, p = idx & 511;
    const float* base = g_S + (size_t)b * 262144 + p;
    float* ob = g_spat + (size_t)b * 262144 + p;
    float mx = -1e30f;
    for (int n = 0; n < 512; n++) mx = fmaxf(mx, base[n * 512]);
    float sum = 0.f;
    for (int n = 0; n < 512; n++) {
        float e = expf(base[n * 512] - mx);
        sum += e;
        ob[n * 512] = e;
    }
    float inv = 1.f / sum;
    for (int n = 0; n < 512; n++) ob[n * 512] *= inv;
}

// ---------------- convA ----------------
__global__ void convA_kernel(const float* __restrict__ cheb) {
    int bk = blockIdx.z;
    int b = bk / 3, k = bk - b * 3;
    int m0 = blockIdx.x * 32, n0 = blockIdx.y * 32;
    __shared__ float tile[32][33];
    const float* ck = cheb + (size_t)k * 262144;
    const float* sp = g_spat + (size_t)b * 262144;
#pragma unroll
    for (int r = 0; r < 4; r++) {
        int m = m0 + threadIdx.y + r * 8;
        int gi = m * 512 + n0 + threadIdx.x;
        tile[threadIdx.y + r * 8][threadIdx.x] = ck[gi] * sp[gi];
    }
    __syncthreads();
    int tid = threadIdx.y * 32 + threadIdx.x;
    unsigned* oh = (unsigned*)g_Ah16;
    unsigned* ol = (unsigned*)g_Al16;
#pragma unroll
    for (int p = 0; p < 2; p++) {
        int pi = tid + p * 256;
        int row = pi >> 4;
        int cp = pi & 15;
        float r0, r1;
        unsigned uh = bf16pair(tile[2 * cp][row], tile[2 * cp + 1][row], r0, r1);
        __nv_bfloat16 l0 = __float2bfloat16(r0), l1 = __float2bfloat16(r1);
        unsigned ulv = (unsigned)__bfloat16_as_ushort(l0) |
                       ((unsigned)__bfloat16_as_ushort(l1) << 16);
        size_t base = ((size_t)bk * 512 + n0 + row) * 256 + (m0 >> 1) + cp;
        oh[base] = uh;
        ol[base] = ulv;
    }
}

// ---------------- convX ----------------
__global__ void convX_kernel(const float* __restrict__ x) {
    int b = blockIdx.z;
    int m0 = blockIdx.x * 32, j0 = blockIdx.y * 32;
    __shared__ float tile[32][33];
    const float* xb = x + (size_t)b * 393216;
#pragma unroll
    for (int r = 0; r < 4; r++) {
        int m = m0 + threadIdx.y + r * 8;
        tile[threadIdx.y + r * 8][threadIdx.x] = xb[m * 768 + j0 + threadIdx.x];
    }
    __syncthreads();
    int tid = threadIdx.y * 32 + threadIdx.x;
    unsigned* oh = (unsigned*)g_Xh16;
    unsigned* ol = (unsigned*)g_Xl16;
#pragma unroll
    for (int p = 0; p < 2; p++) {
        int pi = tid + p * 256;
        int row = pi >> 4;
        int cp = pi & 15;
        float r0, r1;
        unsigned uh = bf16pair(tile[2 * cp][row], tile[2 * cp + 1][row], r0, r1);
        __nv_bfloat16 l0 = __float2bfloat16(r0), l1 = __float2bfloat16(r1);
        unsigned ulv = (unsigned)__bfloat16_as_ushort(l0) |
                       ((unsigned)__bfloat16_as_ushort(l1) << 16);
        size_t base = ((size_t)b * 768 + j0 + row) * 256 + (m0 >> 1) + cp;
        oh[base] = uh;
        ol[base] = ulv;
    }
}

// ---------------- cheb MMA (R8 128-thread version): tile 64n x 64j ----------------
// grid (jt 12, nt 8, b 32), 128 threads (4 warps as 2n x 2j)
__global__ void __launch_bounds__(128) cheb_mma_kernel() {
    __shared__ __align__(16) __nv_bfloat16 sA[3][2][64][40];
    __shared__ __align__(16) __nv_bfloat16 sX[2][64][40];
    int jt = blockIdx.x, nt = blockIdx.y, b = blockIdx.z;
    int n0 = nt * 64, j0 = jt * 64;
    int tid = threadIdx.x;
    int lane = tid & 31, wid = tid >> 5;
    int g = lane >> 2, tg = lane & 3;
    int wn = wid >> 1, wj = wid & 1;

    const __nv_bfloat16* srcA[6];
#pragma unroll
    for (int c = 0; c < 3; c++) {
        size_t base = ((size_t)(b * 3 + c) * 512 + n0) * 512;
        srcA[c * 2] = g_Ah16 + base;
        srcA[c * 2 + 1] = g_Al16 + base;
    }
    const __nv_bfloat16* srcXh = g_Xh16 + ((size_t)b * 768 + j0) * 512;
    const __nv_bfloat16* srcXl = g_Xl16 + ((size_t)b * 768 + j0) * 512;

    float d[3][2][4][4] = {};

    for (int m0 = 0; m0 < 512; m0 += 32) {
        for (int i = tid; i < 1536; i += 128) {
            int rowid = i >> 2, quad = i & 3;
            int ch = rowid >> 6;
            int row = rowid & 63;
            uint4 v = *(const uint4*)(srcA[ch] + (size_t)row * 512 + m0 + quad * 8);
            *(uint4*)&sA[ch >> 1][ch & 1][row][quad * 8] = v;
        }
        for (int i = tid; i < 512; i += 128) {
            int rowid = i >> 2, quad = i & 3;
            int h = rowid >> 6, row = rowid & 63;
            const __nv_bfloat16* sp = (h ? srcXl : srcXh) + (size_t)row * 512 + m0 + quad * 8;
            *(uint4*)&sX[h][row][quad * 8] = *(const uint4*)sp;
        }
        __syncthreads();

#pragma unroll
        for (int kk = 0; kk < 32; kk += 16) {
            unsigned xh[4][2], xl[4][2];
#pragma unroll
            for (int ntile = 0; ntile < 4; ntile++) {
                int jr = wj * 32 + ntile * 8 + g;
                xh[ntile][0] = *(const unsigned*)&sX[0][jr][kk + tg * 2];
                xh[ntile][1] = *(const unsigned*)&sX[0][jr][kk + tg * 2 + 8];
                xl[ntile][0] = *(const unsigned*)&sX[1][jr][kk + tg * 2];
                xl[ntile][1] = *(const unsigned*)&sX[1][jr][kk + tg * 2 + 8];
            }
#pragma unroll
            for (int c = 0; c < 3; c++) {
#pragma unroll
                for (int mt = 0; mt < 2; mt++) {
                    int r0 = wn * 32 + mt * 16 + g;
                    unsigned ah[4], al[4];
                    ah[0] = *(const unsigned*)&sA[c][0][r0][kk + tg * 2];
                    ah[1] = *(const unsigned*)&sA[c][0][r0 + 8][kk + tg * 2];
                    ah[2] = *(const unsigned*)&sA[c][0][r0][kk + tg * 2 + 8];
                    ah[3] = *(const unsigned*)&sA[c][0][r0 + 8][kk + tg * 2 + 8];
                    al[0] = *(const unsigned*)&sA[c][1][r0][kk + tg * 2];
                    al[1] = *(const unsigned*)&sA[c][1][r0 + 8][kk + tg * 2];
                    al[2] = *(const unsigned*)&sA[c][1][r0][kk + tg * 2 + 8];
                    al[3] = *(const unsigned*)&sA[c][1][r0 + 8][kk + tg * 2 + 8];
#pragma unroll
                    for (int ntile = 0; ntile < 4; ntile++) {
                        MMA16816(d[c][mt][ntile], ah, xh[ntile]);
                        MMA16816(d[c][mt][ntile], ah, xl[ntile]);
                        MMA16816(d[c][mt][ntile], al, xh[ntile]);
                    }
                }
            }
        }
        __syncthreads();
    }

#pragma unroll
    for (int c = 0; c < 3; c++) {
        float* Hb = g_H + (size_t)(b * 3 + c) * 512 * 768;
#pragma unroll
        for (int mt = 0; mt < 2; mt++) {
            int nrow = n0 + wn * 32 + mt * 16 + g;
#pragma unroll
            for (int ntile = 0; ntile < 4; ntile++) {
                int jcol = j0 + wj * 32 + ntile * 8 + tg * 2;
                float2 v0 = make_float2(d[c][mt][ntile][0], d[c][mt][ntile][1]);
                float2 v1 = make_float2(d[c][mt][ntile][2], d[c][mt][ntile][3]);
                *(float2*)&Hb[(size_t)nrow * 768 + jcol] = v0;
                *(float2*)&Hb[(size_t)(nrow + 8) * 768 + jcol] = v1;
            }
        }
    }
}

// ---------------- K11: fused epilogue, 192 threads (64ch x 3 t-thirds) ----------------
__global__ void __launch_bounds__(192) final_kernel(
    const float* __restrict__ x, const float* __restrict__ w_cheb,
    const float* __restrict__ time_w, const float* __restrict__ time_b,
    const float* __restrict__ skip_w, const float* __restrict__ skip_b,
    const float* __restrict__ ln_g, const float* __restrict__ ln_b,
    float* __restrict__ out) {
    int bn = blockIdx.x;
    int b = bn >> 9, n = bn & 511;
    int tid = threadIdx.x;  // 192
    int third = tid / 64, ch = tid & 63;
    int tbase = third * 8;
    __shared__ float sH[3 * 32 * 24];
    __shared__ float sx[768];
    __shared__ float sg[64][26];
    __shared__ float sv[64 * 24];
    __shared__ float smu[24], srs[24];

    for (int k = 0; k < 3; k++) {
        const float* src = g_H + ((size_t)(b * 3 + k) * 512 + n) * 768;
        for (int i = tid; i < 768; i += 192) sH[k * 768 + i] = src[i];
    }
    const float* xrow = x + (size_t)bn * 768;
    for (int i = tid; i < 768; i += 192) sx[i] = xrow[i];
    __syncthreads();

    {
        float acc[8];
#pragma unroll
        for (int t = 0; t < 8; t++) acc[t] = 0.f;
        for (int kf = 0; kf < 96; kf++) {
            float w = w_cheb[kf * 64 + ch];
            const float* hr = &sH[kf * 24 + tbase];
#pragma unroll
            for (int t = 0; t < 8; t++) acc[t] += hr[t] * w;
        }
        if (third == 0) sg[ch][0] = 0.f;
        if (third == 2) sg[ch][25] = 0.f;
#pragma unroll
        for (int t = 0; t < 8; t++) sg[ch][tbase + t + 1] = fmaxf(acc[t], 0.f);
    }
    __syncthreads();

    {
        float acc[8];
#pragma unroll
        for (int t = 0; t < 8; t++) acc[t] = 0.f;
        for (int g = 0; g < 64; g++) {
            float w0 = time_w[(ch * 64 + g) * 3 + 0];
            float w1 = time_w[(ch * 64 + g) * 3 + 1];
            float w2 = time_w[(ch * 64 + g) * 3 + 2];
            const float* gr = &sg[g][tbase];
#pragma unroll
            for (int t = 0; t < 8; t++) acc[t] += gr[t] * w0 + gr[t + 1] * w1 + gr[t + 2] * w2;
        }
        for (int f = 0; f < 32; f++) {
            float w = skip_w[ch * 32 + f];
            const float* xr = &sx[f * 24 + tbase];
#pragma unroll
            for (int t = 0; t < 8; t++) acc[t] += xr[t] * w;
        }
        float bias = time_b[ch] + skip_b[ch];
#pragma unroll
        for (int t = 0; t < 8; t++) sv[ch * 24 + tbase + t] = fmaxf(acc[t] + bias, 0.f);
    }
    __syncthreads();

    if (tid < 24) {
        int t = tid;
        float s = 0.f, s2 = 0.f;
        for (int c = 0; c < 64; c++) {
            float v = sv[c * 24 + t];
            s += v;
            s2 += v * v;
        }
        float mu = s * (1.f / 64.f);
        float var = s2 * (1.f / 64.f) - mu * mu;
        smu[t] = mu;
        srs[t] = rsqrtf(var + 1e-5f);
    }
    __syncthreads();

    float* orow = out + (size_t)bn * 1536;
    for (int i = tid; i < 1536; i += 192) {
        int c = i / 24, t = i - c * 24;
        orow[i] = (sv[i] - smu[t]) * srs[t] * ln_g[c] + ln_b[c];
    }
}

// ---------------- launch ----------------
extern "C" void kernel_launch(void* const* d_in, const int* in_sizes, int n_in,
                              void* d_out, int out_size) {
    const float* x       = (const float*)d_in[0];
    const float* cheb    = (const float*)d_in[1];
    const float* w_cheb  = (const float*)d_in[2];
    const float* sa_wa   = (const float*)d_in[3];
    const float* sa_wb   = (const float*)d_in[4];
    const float* sa_wc   = (const float*)d_in[5];
    const float* sa_bias = (const float*)d_in[6];
    const float* sa_proj = (const float*)d_in[7];
    const float* ta_w1   = (const float*)d_in[8];
    const float* ta_w2   = (const float*)d_in[9];
    const float* ta_w3   = (const float*)d_in[10];
    const float* ta_bias = (const float*)d_in[11];
    const float* ta_proj = (const float*)d_in[12];
    const float* time_w  = (const float*)d_in[13];
    const float* time_b  = (const float*)d_in[14];
    const float* skip_w  = (const float*)d_in[15];
    const float* skip_b  = (const float*)d_in[16];
    const float* ln_g    = (const float*)d_in[17];
    const float* ln_b    = (const float*)d_in[18];
    float* out = (float*)d_out;

    // temporal attention
    rhs_t_kernel<<<B_ * N_, 128>>>(x, ta_w3);
    tmp_bt_part_kernel<<<dim3(8, B_), 768>>>(x, ta_w1);
    tmp_bt_reduce_kernel<<<(B_ * 768 + 255) / 256, 256>>>();
    lhs_t_kernel<<<(B_ * T_ * N_ + 255) / 256, 256>>>(ta_w2);
    temporal_attn_kernel<<<B_, 576>>>(ta_bias, ta_proj);
    xtemp_kernel<<<(B_ * N_ * F_ * T_ + 255) / 256, 256>>>(x);

    // operand conversions independent of the attention chain
    convX_kernel<<<dim3(16, 24, B_), dim3(32, 8)>>>(x);
    conv_proj_kernel<<<1024, 256>>>(sa_proj);

    // spatial attention (bf16-split mma S chain)
    spre_kernel<<<B_ * N_, 128>>>(sa_wa, sa_wb, sa_wc);
    spatial_scores_kernel<<<dim3(32, 32, B_), dim3(16, 16)>>>(sa_bias);
    S_mma_kernel<<<dim3(8, 8, B_), 128>>>();
    spat_softmax_kernel<<<(B_ * N_ + 255) / 256, 256>>>();

    // chebyshev graph conv via bf16-split mma.sync
    convA_kernel<<<dim3(16, 16, 96), dim3(32, 8)>>>(cheb);
    cheb_mma_kernel<<<dim3(12, 8, B_), 128>>>();

    // fused epilogue
    final_kernel<<<B_ * N_, 192>>>(x, w_cheb, time_w, time_b, skip_w, skip_b, ln_g, ln_b, out);
}

// round 11
// speedup vs baseline: 1.6647x; 1.6240x over previous
#include <cuda_runtime.h>
#include <cuda_bf16.h>
#include <math.h>

#define B_ 32
#define N_ 512
#define F_ 32
#define T_ 24
#define K_ 3
#define GC_ 64
#define TC_ 64

typedef unsigned long long ull;

// ---------------- scratch (device globals; no allocations allowed) ----------------
__device__ float g_rhs_tT[B_ * T_ * N_];
__device__ float g_tmp_part[B_ * 8 * 768];
__device__ float g_tmp_bt[B_ * T_ * F_];
__device__ float g_lhs_t[B_ * T_ * N_];
__device__ float g_temp_w[B_ * T_ * T_];
__device__ float g_xtemp[B_ * N_ * F_ * T_];
__device__ float g_lhs_s[B_ * N_ * T_];
__device__ float g_rhs_s[B_ * N_ * T_];
__device__ float g_S[B_ * N_ * N_];
__device__ float g_spat[B_ * N_ * N_];
__device__ float g_H[(size_t)B_ * K_ * N_ * F_ * T_];  // [(b*3+k), n, f*24+t]

// bf16 hi/lo operands, row-major [out-dim][m]
__device__ __nv_bfloat16 g_Ah16[(size_t)96 * 512 * 512];  // [(b*3+k)][n][m]
__device__ __nv_bfloat16 g_Al16[(size_t)96 * 512 * 512];
__device__ __nv_bfloat16 g_Xh16[(size_t)32 * 768 * 512];  // [b][j][m]
__device__ __nv_bfloat16 g_Xl16[(size_t)32 * 768 * 512];
// S-chain bf16 operands
__device__ __nv_bfloat16 g_projh[N_ * N_];                // [n][m]
__device__ __nv_bfloat16 g_projl[N_ * N_];
__device__ __nv_bfloat16 g_attnTh[(size_t)B_ * N_ * N_];  // [b][p][m] = attn[m][p]
__device__ __nv_bfloat16 g_attnTl[(size_t)B_ * N_ * N_];

// ---- bf16 mma helper ----
#define MMA16816(d, a, b)                                                            \
    asm volatile(                                                                    \
        "mma.sync.aligned.m16n8k16.row.col.f32.bf16.bf16.f32 "                       \
        "{%0,%1,%2,%3}, {%4,%5,%6,%7}, {%8,%9}, {%0,%1,%2,%3};"                      \
        : "+f"((d)[0]), "+f"((d)[1]), "+f"((d)[2]), "+f"((d)[3])                     \
        : "r"((a)[0]), "r"((a)[1]), "r"((a)[2]), "r"((a)[3]), "r"((b)[0]), "r"((b)[1]))

__device__ __forceinline__ unsigned bf16pair(float v0, float v1, float& r0, float& r1) {
    __nv_bfloat16 h0 = __float2bfloat16(v0), h1 = __float2bfloat16(v1);
    r0 = v0 - __bfloat162float(h0);
    r1 = v1 - __bfloat162float(h1);
    return (unsigned)__bfloat16_as_ushort(h0) | ((unsigned)__bfloat16_as_ushort(h1) << 16);
}

// ---------------- K1: rhs_tT ----------------
__global__ void rhs_t_kernel(const float* __restrict__ x, const float* __restrict__ w3) {
    int bn = blockIdx.x;
    int b = bn >> 9, n = bn & 511;
    __shared__ float row[768];
    const float* xr = x + (size_t)bn * 768;
    for (int i = threadIdx.x; i < 768; i += 128) row[i] = xr[i];
    __syncthreads();
    if (threadIdx.x < 24) {
        int t = threadIdx.x;
        float a = 0.f;
#pragma unroll
        for (int f = 0; f < 32; f++) a += w3[f] * row[f * 24 + t];
        g_rhs_tT[(b * 24 + t) * 512 + n] = a;
    }
}

// ---------------- K2a/b ----------------
__global__ void tmp_bt_part_kernel(const float* __restrict__ x, const float* __restrict__ w1) {
    int chunk = blockIdx.x;
    int b = blockIdx.y;
    int ft = threadIdx.x;
    const float* xb = x + (size_t)b * 512 * 768;
    int n0 = chunk * 64;
    float a = 0.f;
    for (int n = n0; n < n0 + 64; n++) a += w1[n] * xb[n * 768 + ft];
    g_tmp_part[(b * 8 + chunk) * 768 + ft] = a;
}
__global__ void tmp_bt_reduce_kernel() {
    int idx = blockIdx.x * blockDim.x + threadIdx.x;
    if (idx >= B_ * 768) return;
    int b = idx / 768, ft = idx % 768;
    float a = 0.f;
#pragma unroll
    for (int c = 0; c < 8; c++) a += g_tmp_part[(b * 8 + c) * 768 + ft];
    int f = ft / 24, t = ft - f * 24;
    g_tmp_bt[(b * 24 + t) * 32 + f] = a;
}

// ---------------- K3 ----------------
__global__ void lhs_t_kernel(const float* __restrict__ w2) {
    int idx = blockIdx.x * blockDim.x + threadIdx.x;
    if (idx >= B_ * T_ * N_) return;
    int n = idx & 511;
    int bt = idx >> 9;
    float a = 0.f;
#pragma unroll
    for (int f = 0; f < 32; f++) a += g_tmp_bt[bt * 32 + f] * w2[f * 512 + n];
    g_lhs_t[idx] = a;
}

// ---------------- K4 ----------------
__global__ void temporal_attn_kernel(const float* __restrict__ ta_bias,
                                     const float* __restrict__ ta_proj) {
    int b = blockIdx.x;
    int tid = threadIdx.x;
    int t = tid / 24, u = tid - (tid / 24) * 24;
    __shared__ float sL[24][129];
    __shared__ float sR[24][129];
    __shared__ float ssig[576];
    __shared__ float sE[576];

    float p = 0.f;
    for (int n0 = 0; n0 < 512; n0 += 128) {
        __syncthreads();
        for (int i = tid; i < 24 * 128; i += 576) {
            int tt = i >> 7, nn = i & 127;
            sL[tt][nn] = g_lhs_t[(b * 24 + tt) * 512 + n0 + nn];
            sR[tt][nn] = g_rhs_tT[(b * 24 + tt) * 512 + n0 + nn];
        }
        __syncthreads();
#pragma unroll 8
        for (int nn = 0; nn < 128; nn++) p += sL[t][nn] * sR[u][nn];
    }
    ssig[t * 24 + u] = 1.f / (1.f + expf(-(p + ta_bias[t * 24 + u])));
    __syncthreads();

    int s = t;
    float e = 0.f;
#pragma unroll
    for (int tt = 0; tt < 24; tt++) e += ta_proj[s * 24 + tt] * ssig[tt * 24 + u];
    sE[s * 24 + u] = e;
    __syncthreads();

    float mx = -1e30f;
#pragma unroll
    for (int ss = 0; ss < 24; ss++) mx = fmaxf(mx, sE[ss * 24 + u]);
    float sum = 0.f;
#pragma unroll
    for (int ss = 0; ss < 24; ss++) sum += expf(sE[ss * 24 + u] - mx);
    g_temp_w[b * 576 + s * 24 + u] = expf(e - mx) / sum;
}

// ---------------- K5 ----------------
__global__ void xtemp_kernel(const float* __restrict__ x) {
    int idx = blockIdx.x * blockDim.x + threadIdx.x;
    if (idx >= B_ * N_ * F_ * T_) return;
    int u = idx % 24;
    int row = idx / 24;
    int b = row / (512 * 32);
    const float* xr = x + (size_t)row * 24;
    const float* tw = g_temp_w + b * 576;
    float a = 0.f;
#pragma unroll
    for (int t = 0; t < 24; t++) a += xr[t] * tw[t * 24 + u];
    g_xtemp[idx] = a;
}

// ---------------- K6 ----------------
__global__ void spre_kernel(const float* __restrict__ wa, const float* __restrict__ wb,
                            const float* __restrict__ wc) {
    int bn = blockIdx.x;
    __shared__ float row[768];
    __shared__ float st2[32];
    const float* xr = g_xtemp + (size_t)bn * 768;
    for (int i = threadIdx.x; i < 768; i += 128) row[i] = xr[i];
    __syncthreads();
    if (threadIdx.x < 32) {
        int f = threadIdx.x;
        float a = 0.f;
#pragma unroll
        for (int t = 0; t < 24; t++) a += row[f * 24 + t] * wa[t];
        st2[f] = a;
    }
    __syncthreads();
    if (threadIdx.x < 24) {
        int t = threadIdx.x;
        float l = 0.f, r = 0.f;
#pragma unroll
        for (int f = 0; f < 32; f++) {
            l += st2[f] * wb[f * 24 + t];
            r += wc[f] * row[f * 24 + t];
        }
        g_lhs_s[bn * 24 + t] = l;
        g_rhs_s[bn * 24 + t] = r;
    }
}

// ---------------- conv_proj ----------------
__global__ void conv_proj_kernel(const float* __restrict__ proj) {
    int i = blockIdx.x * 256 + threadIdx.x;
    float v = proj[i];
    __nv_bfloat16 h = __float2bfloat16(v);
    g_projh[i] = h;
    g_projl[i] = __float2bfloat16(v - __bfloat162float(h));
}

// ---------------- K7: scores + sigmoid -> transposed bf16 hi/lo attnT[p][m] ----------------
__global__ void spatial_scores_kernel(const float* __restrict__ sa_bias) {
    int b = blockIdx.z;
    int n0 = blockIdx.y * 16, m0 = blockIdx.x * 16;
    __shared__ float sL[16 * 24], sR[16 * 24];
    __shared__ float tv[16][17];
    int tid = threadIdx.y * 16 + threadIdx.x;
    for (int i = tid; i < 384; i += 256) {
        sL[i] = g_lhs_s[(b * 512 + n0 + i / 24) * 24 + i % 24];
        sR[i] = g_rhs_s[(b * 512 + m0 + i / 24) * 24 + i % 24];
    }
    __syncthreads();
    int n = n0 + threadIdx.y, m = m0 + threadIdx.x;
    float s = 0.f;
#pragma unroll
    for (int t = 0; t < 24; t++) s += sL[threadIdx.y * 24 + t] * sR[threadIdx.x * 24 + t];
    float a = 1.f / (1.f + expf(-(s + sa_bias[n * 512 + m])));
    tv[threadIdx.x][threadIdx.y] = a;
    __syncthreads();
    float v = tv[threadIdx.y][threadIdx.x];
    __nv_bfloat16 h = __float2bfloat16(v);
    size_t o = ((size_t)b * 512 + m0 + threadIdx.y) * 512 + n0 + threadIdx.x;
    g_attnTh[o] = h;
    g_attnTl[o] = __float2bfloat16(v - __bfloat162float(h));
}

// ---------------- K8: S via bf16-split mma (128 threads, tile 64n x 64p) ----------------
// grid (pt 8, nt 8, b 32), 4 warps as 2n x 2p
__global__ void __launch_bounds__(128) S_mma_kernel() {
    __shared__ __align__(16) __nv_bfloat16 sP[2][64][40];
    __shared__ __align__(16) __nv_bfloat16 sB[2][64][40];
    int pt = blockIdx.x, nt = blockIdx.y, b = blockIdx.z;
    int n0 = nt * 64, p0 = pt * 64;
    int tid = threadIdx.x;
    int lane = tid & 31, wid = tid >> 5;
    int g = lane >> 2, tg = lane & 3;
    int wn = wid >> 1, wp = wid & 1;

    const __nv_bfloat16* srcP[2] = {g_projh + (size_t)n0 * 512, g_projl + (size_t)n0 * 512};
    const __nv_bfloat16* srcB[2] = {g_attnTh + ((size_t)b * 512 + p0) * 512,
                                    g_attnTl + ((size_t)b * 512 + p0) * 512};

    float d[2][4][4] = {};

    for (int m0 = 0; m0 < 512; m0 += 32) {
        for (int i = tid; i < 512; i += 128) {
            int rowid = i >> 2, quad = i & 3;
            int h = rowid >> 6, row = rowid & 63;
            *(uint4*)&sP[h][row][quad * 8] =
                *(const uint4*)(srcP[h] + (size_t)row * 512 + m0 + quad * 8);
        }
        for (int i = tid; i < 512; i += 128) {
            int rowid = i >> 2, quad = i & 3;
            int h = rowid >> 6, row = rowid & 63;
            *(uint4*)&sB[h][row][quad * 8] =
                *(const uint4*)(srcB[h] + (size_t)row * 512 + m0 + quad * 8);
        }
        __syncthreads();

#pragma unroll
        for (int kk = 0; kk < 32; kk += 16) {
            unsigned bh[4][2], bl[4][2];
#pragma unroll
            for (int p4 = 0; p4 < 4; p4++) {
                int pr = wp * 32 + p4 * 8 + g;
                bh[p4][0] = *(const unsigned*)&sB[0][pr][kk + tg * 2];
                bh[p4][1] = *(const unsigned*)&sB[0][pr][kk + tg * 2 + 8];
                bl[p4][0] = *(const unsigned*)&sB[1][pr][kk + tg * 2];
                bl[p4][1] = *(const unsigned*)&sB[1][pr][kk + tg * 2 + 8];
            }
#pragma unroll
            for (int mt = 0; mt < 2; mt++) {
                int r0 = wn * 32 + mt * 16 + g;
                unsigned ah[4], al[4];
                ah[0] = *(const unsigned*)&sP[0][r0][kk + tg * 2];
                ah[1] = *(const unsigned*)&sP[0][r0 + 8][kk + tg * 2];
                ah[2] = *(const unsigned*)&sP[0][r0][kk + tg * 2 + 8];
                ah[3] = *(const unsigned*)&sP[0][r0 + 8][kk + tg * 2 + 8];
                al[0] = *(const unsigned*)&sP[1][r0][kk + tg * 2];
                al[1] = *(const unsigned*)&sP[1][r0 + 8][kk + tg * 2];
                al[2] = *(const unsigned*)&sP[1][r0][kk + tg * 2 + 8];
                al[3] = *(const unsigned*)&sP[1][r0 + 8][kk + tg * 2 + 8];
#pragma unroll
                for (int p4 = 0; p4 < 4; p4++) {
                    MMA16816(d[mt][p4], ah, bh[p4]);
                    MMA16816(d[mt][p4], ah, bl[p4]);
                    MMA16816(d[mt][p4], al, bh[p4]);
                }
            }
        }
        __syncthreads();
    }

    float* Sb = g_S + (size_t)b * 262144;
#pragma unroll
    for (int mt = 0; mt < 2; mt++) {
        int nrow = n0 + wn * 32 + mt * 16 + g;
#pragma unroll
        for (int p4 = 0; p4 < 4; p4++) {
            int pcol = p0 + wp * 32 + p4 * 8 + tg * 2;
            *(float2*)&Sb[(size_t)nrow * 512 + pcol] = make_float2(d[mt][p4][0], d[mt][p4][1]);
            *(float2*)&Sb[(size_t)(nrow + 8) * 512 + pcol] = make_float2(d[mt][p4][2], d[mt][p4][3]);
        }
    }
}

// ---------------- K9: column softmax ----------------
__global__ void spat_softmax_kernel() {
    int idx = blockIdx.x * blockDim.x + threadIdx.x;
    if (idx >= B_ * N_) return;
    int b = idx >> 9, p = idx & 511;
    const float* base = g_S + (size_t)b * 262144 + p;
    float* ob = g_spat + (size_t)b * 262144 + p;
    float mx = -1e30f;
    for (int n = 0; n < 512; n++) mx = fmaxf(mx, base[n * 512]);
    float sum = 0.f;
    for (int n = 0; n < 512; n++) {
        float e = expf(base[n * 512] - mx);
        sum += e;
        ob[n * 512] = e;
    }
    float inv = 1.f / sum;
    for (int n = 0; n < 512; n++) ob[n * 512] *= inv;
}

// ---------------- convA ----------------
__global__ void convA_kernel(const float* __restrict__ cheb) {
    int bk = blockIdx.z;
    int b = bk / 3, k = bk - b * 3;
    int m0 = blockIdx.x * 32, n0 = blockIdx.y * 32;
    __shared__ float tile[32][33];
    const float* ck = cheb + (size_t)k * 262144;
    const float* sp = g_spat + (size_t)b * 262144;
#pragma unroll
    for (int r = 0; r < 4; r++) {
        int m = m0 + threadIdx.y + r * 8;
        int gi = m * 512 + n0 + threadIdx.x;
        tile[threadIdx.y + r * 8][threadIdx.x] = ck[gi] * sp[gi];
    }
    __syncthreads();
    int tid = threadIdx.y * 32 + threadIdx.x;
    unsigned* oh = (unsigned*)g_Ah16;
    unsigned* ol = (unsigned*)g_Al16;
#pragma unroll
    for (int p = 0; p < 2; p++) {
        int pi = tid + p * 256;
        int row = pi >> 4;
        int cp = pi & 15;
        float r0, r1;
        unsigned uh = bf16pair(tile[2 * cp][row], tile[2 * cp + 1][row], r0, r1);
        __nv_bfloat16 l0 = __float2bfloat16(r0), l1 = __float2bfloat16(r1);
        unsigned ulv = (unsigned)__bfloat16_as_ushort(l0) |
                       ((unsigned)__bfloat16_as_ushort(l1) << 16);
        size_t base = ((size_t)bk * 512 + n0 + row) * 256 + (m0 >> 1) + cp;
        oh[base] = uh;
        ol[base] = ulv;
    }
}

// ---------------- convX ----------------
__global__ void convX_kernel(const float* __restrict__ x) {
    int b = blockIdx.z;
    int m0 = blockIdx.x * 32, j0 = blockIdx.y * 32;
    __shared__ float tile[32][33];
    const float* xb = x + (size_t)b * 393216;
#pragma unroll
    for (int r = 0; r < 4; r++) {
        int m = m0 + threadIdx.y + r * 8;
        tile[threadIdx.y + r * 8][threadIdx.x] = xb[m * 768 + j0 + threadIdx.x];
    }
    __syncthreads();
    int tid = threadIdx.y * 32 + threadIdx.x;
    unsigned* oh = (unsigned*)g_Xh16;
    unsigned* ol = (unsigned*)g_Xl16;
#pragma unroll
    for (int p = 0; p < 2; p++) {
        int pi = tid + p * 256;
        int row = pi >> 4;
        int cp = pi & 15;
        float r0, r1;
        unsigned uh = bf16pair(tile[2 * cp][row], tile[2 * cp + 1][row], r0, r1);
        __nv_bfloat16 l0 = __float2bfloat16(r0), l1 = __float2bfloat16(r1);
        unsigned ulv = (unsigned)__bfloat16_as_ushort(l0) |
                       ((unsigned)__bfloat16_as_ushort(l1) << 16);
        size_t base = ((size_t)b * 768 + j0 + row) * 256 + (m0 >> 1) + cp;
        oh[base] = uh;
        ol[base] = ulv;
    }
}

// ---------------- cheb MMA (128 threads): tile 64n x 64j ----------------
// grid (jt 12, nt 8, b 32), 4 warps as 2n x 2j
__global__ void __launch_bounds__(128) cheb_mma_kernel() {
    __shared__ __align__(16) __nv_bfloat16 sA[3][2][64][40];
    __shared__ __align__(16) __nv_bfloat16 sX[2][64][40];
    int jt = blockIdx.x, nt = blockIdx.y, b = blockIdx.z;
    int n0 = nt * 64, j0 = jt * 64;
    int tid = threadIdx.x;
    int lane = tid & 31, wid = tid >> 5;
    int g = lane >> 2, tg = lane & 3;
    int wn = wid >> 1, wj = wid & 1;

    const __nv_bfloat16* srcA[6];
#pragma unroll
    for (int c = 0; c < 3; c++) {
        size_t base = ((size_t)(b * 3 + c) * 512 + n0) * 512;
        srcA[c * 2] = g_Ah16 + base;
        srcA[c * 2 + 1] = g_Al16 + base;
    }
    const __nv_bfloat16* srcXh = g_Xh16 + ((size_t)b * 768 + j0) * 512;
    const __nv_bfloat16* srcXl = g_Xl16 + ((size_t)b * 768 + j0) * 512;

    float d[3][2][4][4] = {};

    for (int m0 = 0; m0 < 512; m0 += 32) {
        for (int i = tid; i < 1536; i += 128) {
            int rowid = i >> 2, quad = i & 3;
            int ch = rowid >> 6;
            int row = rowid & 63;
            uint4 v = *(const uint4*)(srcA[ch] + (size_t)row * 512 + m0 + quad * 8);
            *(uint4*)&sA[ch >> 1][ch & 1][row][quad * 8] = v;
        }
        for (int i = tid; i < 512; i += 128) {
            int rowid = i >> 2, quad = i & 3;
            int h = rowid >> 6, row = rowid & 63;
            const __nv_bfloat16* sp = (h ? srcXl : srcXh) + (size_t)row * 512 + m0 + quad * 8;
            *(uint4*)&sX[h][row][quad * 8] = *(const uint4*)sp;
        }
        __syncthreads();

#pragma unroll
        for (int kk = 0; kk < 32; kk += 16) {
            unsigned xh[4][2], xl[4][2];
#pragma unroll
            for (int ntile = 0; ntile < 4; ntile++) {
                int jr = wj * 32 + ntile * 8 + g;
                xh[ntile][0] = *(const unsigned*)&sX[0][jr][kk + tg * 2];
                xh[ntile][1] = *(const unsigned*)&sX[0][jr][kk + tg * 2 + 8];
                xl[ntile][0] = *(const unsigned*)&sX[1][jr][kk + tg * 2];
                xl[ntile][1] = *(const unsigned*)&sX[1][jr][kk + tg * 2 + 8];
            }
#pragma unroll
            for (int c = 0; c < 3; c++) {
#pragma unroll
                for (int mt = 0; mt < 2; mt++) {
                    int r0 = wn * 32 + mt * 16 + g;
                    unsigned ah[4], al[4];
                    ah[0] = *(const unsigned*)&sA[c][0][r0][kk + tg * 2];
                    ah[1] = *(const unsigned*)&sA[c][0][r0 + 8][kk + tg * 2];
                    ah[2] = *(const unsigned*)&sA[c][0][r0][kk + tg * 2 + 8];
                    ah[3] = *(const unsigned*)&sA[c][0][r0 + 8][kk + tg * 2 + 8];
                    al[0] = *(const unsigned*)&sA[c][1][r0][kk + tg * 2];
                    al[1] = *(const unsigned*)&sA[c][1][r0 + 8][kk + tg * 2];
                    al[2] = *(const unsigned*)&sA[c][1][r0][kk + tg * 2 + 8];
                    al[3] = *(const unsigned*)&sA[c][1][r0 + 8][kk + tg * 2 + 8];
#pragma unroll
                    for (int ntile = 0; ntile < 4; ntile++) {
                        MMA16816(d[c][mt][ntile], ah, xh[ntile]);
                        MMA16816(d[c][mt][ntile], ah, xl[ntile]);
                        MMA16816(d[c][mt][ntile], al, xh[ntile]);
                    }
                }
            }
        }
        __syncthreads();
    }

#pragma unroll
    for (int c = 0; c < 3; c++) {
        float* Hb = g_H + (size_t)(b * 3 + c) * 512 * 768;
#pragma unroll
        for (int mt = 0; mt < 2; mt++) {
            int nrow = n0 + wn * 32 + mt * 16 + g;
#pragma unroll
            for (int ntile = 0; ntile < 4; ntile++) {
                int jcol = j0 + wj * 32 + ntile * 8 + tg * 2;
                float2 v0 = make_float2(d[c][mt][ntile][0], d[c][mt][ntile][1]);
                float2 v1 = make_float2(d[c][mt][ntile][2], d[c][mt][ntile][3]);
                *(float2*)&Hb[(size_t)nrow * 768 + jcol] = v0;
                *(float2*)&Hb[(size_t)(nrow + 8) * 768 + jcol] = v1;
            }
        }
    }
}

// ---------------- K11: fused epilogue (R8 128-thread version) ----------------
__global__ void final_kernel(const float* __restrict__ x, const float* __restrict__ w_cheb,
                             const float* __restrict__ time_w, const float* __restrict__ time_b,
                             const float* __restrict__ skip_w, const float* __restrict__ skip_b,
                             const float* __restrict__ ln_g, const float* __restrict__ ln_b,
                             float* __restrict__ out) {
    int bn = blockIdx.x;
    int b = bn >> 9, n = bn & 511;
    int tid = threadIdx.x;  // 128
    int ch = tid >> 1, half = tid & 1;
    int tbase = half * 12;
    __shared__ float sH[3 * 32 * 24];
    __shared__ float sx[768];
    __shared__ float sg[64][26];
    __shared__ float sv[64 * 24];
    __shared__ float smu[24], srs[24];

    for (int k = 0; k < 3; k++) {
        const float* src = g_H + ((size_t)(b * 3 + k) * 512 + n) * 768;
        for (int i = tid; i < 768; i += 128) sH[k * 768 + i] = src[i];
    }
    const float* xrow = x + (size_t)bn * 768;
    for (int i = tid; i < 768; i += 128) sx[i] = xrow[i];
    __syncthreads();

    {
        float acc[12];
#pragma unroll
        for (int t = 0; t < 12; t++) acc[t] = 0.f;
        for (int kf = 0; kf < 96; kf++) {
            float w = w_cheb[kf * 64 + ch];
            const float* hr = &sH[kf * 24 + tbase];
#pragma unroll
            for (int t = 0; t < 12; t++) acc[t] += hr[t] * w;
        }
        if (half == 0) { sg[ch][0] = 0.f; sg[ch][25] = 0.f; }
#pragma unroll
        for (int t = 0; t < 12; t++) sg[ch][tbase + t + 1] = fmaxf(acc[t], 0.f);
    }
    __syncthreads();

    {
        float acc[12];
#pragma unroll
        for (int t = 0; t < 12; t++) acc[t] = 0.f;
        for (int g = 0; g < 64; g++) {
            float w0 = time_w[(ch * 64 + g) * 3 + 0];
            float w1 = time_w[(ch * 64 + g) * 3 + 1];
            float w2 = time_w[(ch * 64 + g) * 3 + 2];
            const float* gr = &sg[g][tbase];
#pragma unroll
            for (int t = 0; t < 12; t++) acc[t] += gr[t] * w0 + gr[t + 1] * w1 + gr[t + 2] * w2;
        }
        for (int f = 0; f < 32; f++) {
            float w = skip_w[ch * 32 + f];
            const float* xr = &sx[f * 24 + tbase];
#pragma unroll
            for (int t = 0; t < 12; t++) acc[t] += xr[t] * w;
        }
        float bias = time_b[ch] + skip_b[ch];
#pragma unroll
        for (int t = 0; t < 12; t++) sv[ch * 24 + tbase + t] = fmaxf(acc[t] + bias, 0.f);
    }
    __syncthreads();

    if (tid < 24) {
        int t = tid;
        float s = 0.f, s2 = 0.f;
        for (int c = 0; c < 64; c++) {
            float v = sv[c * 24 + t];
            s += v;
            s2 += v * v;
        }
        float mu = s * (1.f / 64.f);
        float var = s2 * (1.f / 64.f) - mu * mu;
        smu[t] = mu;
        srs[t] = rsqrtf(var + 1e-5f);
    }
    __syncthreads();

    float* orow = out + (size_t)bn * 1536;
    for (int i = tid; i < 1536; i += 128) {
        int c = i / 24, t = i - c * 24;
        orow[i] = (sv[i] - smu[t]) * srs[t] * ln_g[c] + ln_b[c];
    }
}

// ---------------- launch ----------------
extern "C" void kernel_launch(void* const* d_in, const int* in_sizes, int n_in,
                              void* d_out, int out_size) {
    const float* x       = (const float*)d_in[0];
    const float* cheb    = (const float*)d_in[1];
    const float* w_cheb  = (const float*)d_in[2];
    const float* sa_wa   = (const float*)d_in[3];
    const float* sa_wb   = (const float*)d_in[4];
    const float* sa_wc   = (const float*)d_in[5];
    const float* sa_bias = (const float*)d_in[6];
    const float* sa_proj = (const float*)d_in[7];
    const float* ta_w1   = (const float*)d_in[8];
    const float* ta_w2   = (const float*)d_in[9];
    const float* ta_w3   = (const float*)d_in[10];
    const float* ta_bias = (const float*)d_in[11];
    const float* ta_proj = (const float*)d_in[12];
    const float* time_w  = (const float*)d_in[13];
    const float* time_b  = (const float*)d_in[14];
    const float* skip_w  = (const float*)d_in[15];
    const float* skip_b  = (const float*)d_in[16];
    const float* ln_g    = (const float*)d_in[17];
    const float* ln_b    = (const float*)d_in[18];
    float* out = (float*)d_out;

    // temporal attention
    rhs_t_kernel<<<B_ * N_, 128>>>(x, ta_w3);
    tmp_bt_part_kernel<<<dim3(8, B_), 768>>>(x, ta_w1);
    tmp_bt_reduce_kernel<<<(B_ * 768 + 255) / 256, 256>>>();
    lhs_t_kernel<<<(B_ * T_ * N_ + 255) / 256, 256>>>(ta_w2);
    temporal_attn_kernel<<<B_, 576>>>(ta_bias, ta_proj);
    xtemp_kernel<<<(B_ * N_ * F_ * T_ + 255) / 256, 256>>>(x);

    // operand conversions independent of the attention chain
    convX_kernel<<<dim3(16, 24, B_), dim3(32, 8)>>>(x);
    conv_proj_kernel<<<1024, 256>>>(sa_proj);

    // spatial attention (bf16-split mma S chain)
    spre_kernel<<<B_ * N_, 128>>>(sa_wa, sa_wb, sa_wc);
    spatial_scores_kernel<<<dim3(32, 32, B_), dim3(16, 16)>>>(sa_bias);
    S_mma_kernel<<<dim3(8, 8, B_), 128>>>();
    spat_softmax_kernel<<<(B_ * N_ + 255) / 256, 256>>>();

    // chebyshev graph conv via bf16-split mma.sync
    convA_kernel<<<dim3(16, 16, 96), dim3(32, 8)>>>(cheb);
    cheb_mma_kernel<<<dim3(12, 8, B_), 128>>>();

    // fused epilogue
    final_kernel<<<B_ * N_, 128>>>(x, w_cheb, time_w, time_b, skip_w, skip_b, ln_g, ln_b, out);
}